// round 9
// baseline (speedup 1.0000x reference)
#include <cuda_runtime.h>
#include <cuda_bf16.h>
#include <cstdint>

#define SEQ   512
#define BATCH 64
#define DIM   1024
#define HID   1024
#define NJ    4096            // 4 gates * HID
#define MROWS (SEQ*BATCH)     // 32768

// ---------------- scratch (static device allocs only) ----------------
__device__ float g_G[(size_t)SEQ * BATCH * NJ];          // [m][j] fp32 (x@Wx + biases)
__device__ __nv_bfloat16 g_Xs[(size_t)MROWS * 2048];     // [m][hi(1024)|lo(1024)]
__device__ __nv_bfloat16 g_Ws[(size_t)NJ * 2048];        // [j][hi|lo]  (Wx^T)
__device__ __nv_bfloat16 g_Whs[(size_t)NJ * 2048];       // [cb][hi|lo] (Wh^T, block-packed)
__device__ __nv_bfloat16 g_Hs[2][(size_t)BATCH * 2048];  // h staging [buf][b][hi|lo]
__device__ float g_bias[NJ];                             // bx+bh (gate-major j)
#define RB 128
__device__ volatile unsigned int g_flags[RB];            // per-block step flags (monotonic)

struct GatePtrs {
    const float* Wx[4];
    const float* Wh[4];
    const float* bx[4];
    const float* bh[4];
};

// ---------------- small helpers ----------------
__device__ __forceinline__ uint32_t smem_to_u32(const void* p) {
    uint32_t a;
    asm("{ .reg .u64 t; cvta.to.shared.u64 t, %1; cvt.u32.u64 %0, t; }"
        : "=r"(a) : "l"(p));
    return a;
}
__device__ __forceinline__ void cp_async16(uint32_t saddr, const void* g) {
    asm volatile("cp.async.cg.shared.global [%0], [%1], 16;"
                 :: "r"(saddr), "l"(g) : "memory");
}
__device__ __forceinline__ void cp_commit() {
    asm volatile("cp.async.commit_group;" ::: "memory");
}
#define CP_WAIT2() asm volatile("cp.async.wait_group 2;" ::: "memory")
#define CP_WAIT0() asm volatile("cp.async.wait_group 0;" ::: "memory")

#define LDSM_X4(r0, r1, r2, r3, addr) \
    asm volatile("ldmatrix.sync.aligned.m8n8.x4.shared.b16 {%0,%1,%2,%3}, [%4];" \
        : "=r"(r0), "=r"(r1), "=r"(r2), "=r"(r3) : "r"(addr))

__device__ __forceinline__ void mma_bf16(float* c, const uint32_t* a, const uint32_t* b) {
    asm volatile(
        "mma.sync.aligned.m16n8k16.row.col.f32.bf16.bf16.f32 "
        "{%0,%1,%2,%3}, {%4,%5,%6,%7}, {%8,%9}, {%0,%1,%2,%3};"
        : "+f"(c[0]), "+f"(c[1]), "+f"(c[2]), "+f"(c[3])
        : "r"(a[0]), "r"(a[1]), "r"(a[2]), "r"(a[3]), "r"(b[0]), "r"(b[1]));
}

// smem addr with xor swizzle on 16B chunks (4 chunks per 64B row)
__device__ __forceinline__ uint32_t swz(uint32_t base, int row, int chunk) {
    return base + row * 64 + (((uint32_t)chunk ^ (((uint32_t)row >> 1) & 3)) << 4);
}

__device__ __forceinline__ float sigm(float v) {
    return 1.0f / (1.0f + expf(-v));
}

__device__ __forceinline__ void named_bar(int id, int nthreads) {
    asm volatile("bar.sync %0, %1;" :: "r"(id), "r"(nthreads) : "memory");
}

// ---------------- pack kernels ----------------
__global__ void pack_bias_kernel(GatePtrs p) {
    int idx = blockIdx.x * blockDim.x + threadIdx.x;   // 0..4095, j = g*1024+n
    int g = idx >> 10, n = idx & 1023;
    g_bias[idx] = p.bx[g][n] + p.bh[g][n];
}

__global__ void pack_xs_kernel(const float* __restrict__ x) {
    int m = blockIdx.x;
    int k = threadIdx.x * 4;
    float4 v = *(const float4*)(x + (size_t)m * DIM + k);
    __nv_bfloat16 h0 = __float2bfloat16(v.x);
    __nv_bfloat16 h1 = __float2bfloat16(v.y);
    __nv_bfloat16 h2 = __float2bfloat16(v.z);
    __nv_bfloat16 h3 = __float2bfloat16(v.w);
    __nv_bfloat16 l0 = __float2bfloat16(v.x - __bfloat162float(h0));
    __nv_bfloat16 l1 = __float2bfloat16(v.y - __bfloat162float(h1));
    __nv_bfloat16 l2 = __float2bfloat16(v.z - __bfloat162float(h2));
    __nv_bfloat16 l3 = __float2bfloat16(v.w - __bfloat162float(h3));
    size_t base = (size_t)m * 2048 + k;
    *(__nv_bfloat162*)(g_Xs + base)            = __halves2bfloat162(h0, h1);
    *(__nv_bfloat162*)(g_Xs + base + 2)        = __halves2bfloat162(h2, h3);
    *(__nv_bfloat162*)(g_Xs + base + 1024)     = __halves2bfloat162(l0, l1);
    *(__nv_bfloat162*)(g_Xs + base + 1024 + 2) = __halves2bfloat162(l2, l3);
}

__global__ void pack_ws_kernel(GatePtrs p) {
    __shared__ float s[32][33];
    int kt = blockIdx.x, nt = blockIdx.y, g = blockIdx.z;
    int tx = threadIdx.x & 31;
    int ty = threadIdx.x >> 5;
#pragma unroll
    for (int i = 0; i < 4; i++) {
        int r = ty + i * 8;
        s[r][tx] = p.Wx[g][(size_t)(kt * 32 + r) * 1024 + nt * 32 + tx];
    }
    __syncthreads();
#pragma unroll
    for (int i = 0; i < 4; i++) {
        int r2 = ty + i * 8;
        float v = s[tx][r2];
        __nv_bfloat16 hi = __float2bfloat16(v);
        __nv_bfloat16 lo = __float2bfloat16(v - __bfloat162float(hi));
        size_t j = (size_t)g * 1024 + nt * 32 + r2;
        size_t kcol = kt * 32 + tx;
        g_Ws[j * 2048 + kcol]        = hi;
        g_Ws[j * 2048 + 1024 + kcol] = lo;
    }
}

// Wh -> bf16 hi/lo split, block-packed: cb = blk*32 + (g*8+cc)
__global__ void pack_whs_kernel(GatePtrs p) {
    int cb = blockIdx.x;            // 0..4095
    int blk = cb >> 5;
    int c = cb & 31;
    int g = c >> 3;
    int col = blk * 8 + (c & 7);
    const float* W = p.Wh[g];
    int k0 = threadIdx.x * 4;
#pragma unroll
    for (int q = 0; q < 4; q++) {
        int k = k0 + q;
        float v = W[(size_t)k * 1024 + col];
        __nv_bfloat16 hi = __float2bfloat16(v);
        __nv_bfloat16 lo = __float2bfloat16(v - __bfloat162float(hi));
        g_Whs[(size_t)cb * 2048 + k]        = hi;
        g_Whs[(size_t)cb * 2048 + 1024 + k] = lo;
    }
}

// ---------------- xproj: HMMA (mma.sync bf16) GEMM (proven R4 version) ----------------
#define BMT 256
#define BNT 128
#define BKT 32
#define STAGE_BYTES ((BMT + BNT) * BKT * 2)   // 24576
#define XP_SMEM (4 * STAGE_BYTES)             // 98304
#define NKI 96                                // 3072 / 32

__global__ __launch_bounds__(512, 1) void xproj_mma_kernel() {
    extern __shared__ char smem[];
    const uint32_t sbase = smem_to_u32(smem);
    const int tid = threadIdx.x;
    const int wid = tid >> 5;
    const int lid = tid & 31;

    const int mtile = blockIdx.x >> 5;
    const int ntile = blockIdx.x & 31;
    const int m0 = mtile * BMT;
    const int n0 = ntile * BNT;

    const int wm = wid >> 2;
    const int wn = wid & 3;

    int aRow[4], aSw[4];
#pragma unroll
    for (int mf = 0; mf < 4; mf++) {
        int r = wm * 64 + mf * 16 + (((lid >> 3) & 1) << 3) + (lid & 7);
        aRow[mf] = r * 64;
        aSw[mf] = (r >> 1) & 3;
    }
    const int aBit = lid >> 4;
    int bRow[2], bSw[2];
#pragma unroll
    for (int np = 0; np < 2; np++) {
        int r = wn * 32 + np * 16 + (((lid >> 4) & 1) << 3) + (lid & 7);
        bRow[np] = r * 64;
        bSw[np] = (r >> 1) & 3;
    }
    const int bBit = (lid >> 3) & 1;

    float acc[4][4][4];
#pragma unroll
    for (int mf = 0; mf < 4; mf++)
#pragma unroll
        for (int nf = 0; nf < 4; nf++)
#pragma unroll
            for (int q = 0; q < 4; q++) acc[mf][nf][q] = 0.0f;

    auto load_stage = [&](int kt, int st) {
        int seg = kt >> 5;
        int koff = (kt & 31) << 5;
        int a_col = koff + ((seg == 2) ? 1024 : 0);
        int b_col = koff + ((seg == 1) ? 1024 : 0);
        uint32_t sa = sbase + st * STAGE_BYTES;
        uint32_t sb = sa + BMT * BKT * 2;
#pragma unroll
        for (int i = 0; i < 3; i++) {
            int task = tid + i * 512;
            if (task < 1024) {
                int row = task >> 2, ch = task & 3;
                cp_async16(swz(sa, row, ch),
                           g_Xs + (size_t)(m0 + row) * 2048 + a_col + ch * 8);
            } else {
                int t2 = task - 1024;
                int row = t2 >> 2, ch = t2 & 3;
                cp_async16(swz(sb, row, ch),
                           g_Ws + (size_t)(n0 + row) * 2048 + b_col + ch * 8);
            }
        }
        cp_commit();
    };

    load_stage(0, 0);
    load_stage(1, 1);
    load_stage(2, 2);

    for (int kt = 0; kt < NKI; kt++) {
        CP_WAIT2();
        __syncthreads();
        if (kt + 3 < NKI) load_stage(kt + 3, (kt + 3) & 3);
        else cp_commit();

        uint32_t sa = sbase + (kt & 3) * STAGE_BYTES;
        uint32_t sb = sa + BMT * BKT * 2;

#pragma unroll
        for (int k16 = 0; k16 < 2; k16++) {
            uint32_t bf[4][2];
#pragma unroll
            for (int np = 0; np < 2; np++) {
                uint32_t addr = sb + bRow[np]
                              + (((uint32_t)(k16 * 2 + bBit) ^ bSw[np]) << 4);
                uint32_t r0, r1, r2, r3;
                LDSM_X4(r0, r1, r2, r3, addr);
                bf[np * 2][0] = r0; bf[np * 2][1] = r1;
                bf[np * 2 + 1][0] = r2; bf[np * 2 + 1][1] = r3;
            }
#pragma unroll
            for (int mf = 0; mf < 4; mf++) {
                uint32_t af[4];
                uint32_t addr = sa + aRow[mf]
                              + (((uint32_t)(k16 * 2 + aBit) ^ aSw[mf]) << 4);
                LDSM_X4(af[0], af[1], af[2], af[3], addr);
#pragma unroll
                for (int nf = 0; nf < 4; nf++)
                    mma_bf16(acc[mf][nf], af, bf[nf]);
            }
        }
    }

    const int row_base = m0 + wm * 64 + (lid >> 2);
    const int col_base = n0 + wn * 32 + (lid & 3) * 2;
#pragma unroll
    for (int nf = 0; nf < 4; nf++) {
        int col = col_base + nf * 8;
        float2 bb = *(const float2*)&g_bias[col];
#pragma unroll
        for (int mf = 0; mf < 4; mf++) {
            int r = row_base + mf * 16;
            float2 v0 = make_float2(acc[mf][nf][0] + bb.x, acc[mf][nf][1] + bb.y);
            float2 v1 = make_float2(acc[mf][nf][2] + bb.x, acc[mf][nf][3] + bb.y);
            *(float2*)&g_G[(size_t)r * NJ + col]       = v0;
            *(float2*)&g_G[(size_t)(r + 8) * NJ + col] = v1;
        }
    }
}

// ---------------- persistent recurrence v5: distributed-flag grid barrier ----------------
// 128 blocks x 512 threads. Block owns 8 hidden cols (32 gate-cols).
// warp = (wm 0..3 [m16], wn 0..1 [n16], ks 0..1 [K half]).
// Wh split resident in SMEM. A(h) chunks staged per (wm,ks) pair via 4-stage
// cp.async ring (depth-3), one 64-thread named barrier per chunk.
// Grid barrier: per-block monotonic flags (parallel stores, distributed polling).
#define RSM_B     0            // 64 chunks * 2048B = 131072
#define RSM_A     131072       // 8 pairs * 4 stages * 2048B = 65536
#define RSM_PRE   196608       // 64*33 floats = 8448
#define RSM_PRE2  205056       // 64*33 floats = 8448
#define RSM_TOTAL 213504

__global__ __launch_bounds__(512, 1) void lstm_rec_kernel(float* __restrict__ out) {
    extern __shared__ char smem[];
    const uint32_t sbase = smem_to_u32(smem);
    const uint32_t Bbase = sbase + RSM_B;
    float* pre_s  = (float*)(smem + RSM_PRE);    // ks=0 partials [64][33]
    float* pre2_s = (float*)(smem + RSM_PRE2);   // ks=1 partials [64][33]

    const int tid = threadIdx.x;
    const int wid = tid >> 5;
    const int lid = tid & 31;
    const int blk = blockIdx.x;

    // graph-replay-safe barrier base: all flags equal at kernel entry
    const unsigned base = g_flags[blk];

    // warp coords: wid = ks*8 + wn*4 + wm
    const int wm = wid & 3;
    const int wn = (wid >> 2) & 1;
    const int ks = wid >> 3;
    const int pairid = ks * 4 + wm;                  // 0..7
    const uint32_t Apair = sbase + RSM_A + pairid * 8192;

    // ldmatrix lane addresses (A region: 16 rows x 64B; B chunks: 32 rows x 64B)
    const int arow = (((lid >> 3) & 1) << 3) + (lid & 7);
    const int aR = arow * 64, aS = (arow >> 1) & 3;
    const int aBit = lid >> 4;
    const int brow = wn * 16 + (((lid >> 4) & 1) << 3) + (lid & 7);
    const int bR = brow * 64, bS = (brow >> 1) & 3;
    const int bBit = (lid >> 3) & 1;

    // gate-thread mapping: 512 threads -> (b 0..63, oc 0..7)
    const int oc = tid & 7;
    const int b = tid >> 3;
    const int ncol = blk * 8 + oc;

    float* out_hseq = out;
    float* out_h = out + (size_t)SEQ * BATCH * HID;
    float* out_c = out_h + BATCH * HID;

    // ---- preload Wh split into smem: 64 chunks of 32 rows x 32 k ----
#pragma unroll 4
    for (int i = 0; i < 16; i++) {
        int task = tid + i * 512;           // 0..8191
        int chunk = task >> 7;
        int rem = task & 127;
        int r = rem >> 2;
        int ci = rem & 3;
        int col = (chunk < 32) ? chunk * 32 : 1024 + (chunk - 32) * 32;
        cp_async16(swz(Bbase + chunk * 2048, r, ci),
                   g_Whs + (size_t)(blk * 32 + r) * 2048 + col + ci * 8);
    }
    cp_commit();
    CP_WAIT0();
    __syncthreads();

    float cst = 0.0f;    // per-thread cell state (one (b, ncol) pair)

    for (int t = 0; t < SEQ; t++) {
        const __nv_bfloat16* hprev = g_Hs[(t - 1) & 1];

        // prefetch G[t] (x@Wx + biases) per gate
        float gpre[4];
        {
            const float* Gt = g_G + (size_t)t * BATCH * NJ + (size_t)b * NJ + ncol;
#pragma unroll
            for (int g = 0; g < 4; g++)
                gpre[g] = __ldg(Gt + g * 1024);
        }

        // 3 independent accumulator sets x 2 col-fragments
        float a_hh[2][4], a_lh[2][4], a_hl[2][4];
#pragma unroll
        for (int nf = 0; nf < 2; nf++)
#pragma unroll
            for (int q = 0; q < 4; q++) {
                a_hh[nf][q] = 0.0f;
                a_lh[nf][q] = 0.0f;
                a_hl[nf][q] = 0.0f;
            }

        if (t > 0) {
            // per-warp chunk loader (pair-shared region; each warp loads half)
            auto load_chunk = [&](int c) {
                if (c < 16) {
                    uint32_t st = Apair + (c & 3) * 2048;
                    int k0 = ks * 512 + c * 32;
#pragma unroll
                    for (int i = 0; i < 2; i++) {
                        int idx = wn * 64 + lid + i * 32;    // 0..127 across pair
                        int half = idx >> 6;                 // 0 hi, 1 lo
                        int rr = idx & 63;
                        int r = rr >> 2, ch = rr & 3;
                        cp_async16(swz(st + half * 1024, r, ch),
                                   hprev + (size_t)(wm * 16 + r) * 2048
                                         + half * 1024 + k0 + ch * 8);
                    }
                }
                cp_commit();
            };

            // depth-3 prefetch fills the 4-stage ring
            load_chunk(0);
            load_chunk(1);
            load_chunk(2);

            for (int c = 0; c < 16; c++) {
                CP_WAIT2();                 // chunk c landed; c+1, c+2 in flight
                named_bar(1 + pairid, 64);
                load_chunk(c + 3);          // issue into slot (c+3)&3

                uint32_t AH = Apair + (c & 3) * 2048;
                uint32_t AL = AH + 1024;
                uint32_t BH = Bbase + (ks * 16 + c) * 2048;
                uint32_t BL = Bbase + (32 + ks * 16 + c) * 2048;

#pragma unroll
                for (int k16 = 0; k16 < 2; k16++) {
                    uint32_t aOff = (((uint32_t)(k16 * 2 + aBit) ^ aS) << 4);
                    uint32_t bOff = (((uint32_t)(k16 * 2 + bBit) ^ bS) << 4);
                    uint32_t af[4], al[4];
                    LDSM_X4(af[0], af[1], af[2], af[3], AH + aR + aOff);
                    LDSM_X4(al[0], al[1], al[2], al[3], AL + aR + aOff);
                    uint32_t r0, r1, r2, r3;
                    LDSM_X4(r0, r1, r2, r3, BH + bR + bOff);
                    uint32_t bh0[2] = {r0, r1}, bh1[2] = {r2, r3};
                    // 6 independent accumulation chains
                    mma_bf16(a_hh[0], af, bh0);
                    mma_bf16(a_hh[1], af, bh1);
                    mma_bf16(a_lh[0], al, bh0);
                    mma_bf16(a_lh[1], al, bh1);
                    LDSM_X4(r0, r1, r2, r3, BL + bR + bOff);
                    uint32_t bl0[2] = {r0, r1}, bl1[2] = {r2, r3};
                    mma_bf16(a_hl[0], af, bl0);
                    mma_bf16(a_hl[1], af, bl1);
                }
            }
        }

        // write partial fragments (sum the 3 term-accumulators here)
        {
            float* dst = ks ? pre2_s : pre_s;
            int r = wm * 16 + (lid >> 2);
            int cb2 = wn * 16 + (lid & 3) * 2;
#pragma unroll
            for (int nf = 0; nf < 2; nf++) {
                int c = cb2 + nf * 8;
                dst[r * 33 + c]           = a_hh[nf][0] + a_lh[nf][0] + a_hl[nf][0];
                dst[r * 33 + c + 1]       = a_hh[nf][1] + a_lh[nf][1] + a_hl[nf][1];
                dst[(r + 8) * 33 + c]     = a_hh[nf][2] + a_lh[nf][2] + a_hl[nf][2];
                dst[(r + 8) * 33 + c + 1] = a_hh[nf][3] + a_lh[nf][3] + a_hl[nf][3];
            }
        }
        __syncthreads();

        // gate math: pre cols [f0..7 | i0..7 | o0..7 | g0..7]
        {
            float pf = pre_s[b * 33 + oc]      + pre2_s[b * 33 + oc]      + gpre[0];
            float pi = pre_s[b * 33 + 8 + oc]  + pre2_s[b * 33 + 8 + oc]  + gpre[1];
            float po = pre_s[b * 33 + 16 + oc] + pre2_s[b * 33 + 16 + oc] + gpre[2];
            float pg = pre_s[b * 33 + 24 + oc] + pre2_s[b * 33 + 24 + oc] + gpre[3];

            float f = sigm(pf);
            float i = sigm(pi);
            float o = sigm(po);
            float g = tanhf(pg);
            cst = f * cst + i * g;
            float h = o * tanhf(cst);

            // h staging first (critical path for next step), then output
            __nv_bfloat16* Hc = g_Hs[t & 1];
            __nv_bfloat16 hhi = __float2bfloat16(h);
            Hc[(size_t)b * 2048 + ncol]        = hhi;
            Hc[(size_t)b * 2048 + 1024 + ncol] =
                __float2bfloat16(h - __bfloat162float(hhi));

            out_hseq[(size_t)t * BATCH * HID + (size_t)b * HID + ncol] = h;

            if (t == SEQ - 1) {
                out_h[(size_t)b * HID + ncol] = h;
                out_c[(size_t)b * HID + ncol] = cst;
            }
        }

        // distributed-flag grid barrier (no single-address atomic serialization)
        if (t < SEQ - 1) {
            __threadfence();            // order h stores before flag store
            __syncthreads();
            const unsigned want = base + (unsigned)t + 1u;
            if (tid == 0) g_flags[blk] = want;
            if (tid < RB) {
                while (g_flags[tid] < want) { __nanosleep(32); }
            }
            __threadfence();            // acquire: h visible before cp.async reads
            __syncthreads();
        }
    }
}

// ---------------- launch ----------------
extern "C" void kernel_launch(void* const* d_in, const int* in_sizes, int n_in,
                              void* d_out, int out_size) {
    const float* x = nullptr;
    const float* W[8] = {};
    const float* Bv[8] = {};
    int wi = 0, bi = 0;
    for (int i = 0; i < n_in; i++) {
        long long sz = in_sizes[i];
        if (sz == (long long)SEQ * BATCH * DIM) {
            x = (const float*)d_in[i];
        } else if (sz == (long long)DIM * HID) {
            if (wi < 8) W[wi++] = (const float*)d_in[i];
        } else if (sz == HID) {
            if (bi < 8) Bv[bi++] = (const float*)d_in[i];
        }
    }
    if (!x || wi != 8 || bi != 8) return;

    GatePtrs p;
    for (int g = 0; g < 4; g++) {
        p.Wx[g] = W[g];
        p.Wh[g] = W[4 + g];
        p.bx[g] = Bv[g];
        p.bh[g] = Bv[4 + g];
    }

    float* outf = (float*)d_out;

    cudaFuncSetAttribute(xproj_mma_kernel,
                         cudaFuncAttributeMaxDynamicSharedMemorySize, XP_SMEM);
    cudaFuncSetAttribute(lstm_rec_kernel,
                         cudaFuncAttributeMaxDynamicSharedMemorySize, RSM_TOTAL);

    // order chosen so the profiler's capture slot (4th launch) lands on xproj
    pack_xs_kernel<<<MROWS, 256>>>(x);
    dim3 wgrid(32, 32, 4);
    pack_ws_kernel<<<wgrid, 256>>>(p);
    pack_bias_kernel<<<4, 1024>>>(p);

    xproj_mma_kernel<<<128 * 32, 512, XP_SMEM>>>();

    pack_whs_kernel<<<NJ, 256>>>(p);

    lstm_rec_kernel<<<RB, 512, RSM_TOTAL>>>(outf);
}

// round 10
// speedup vs baseline: 1.5835x; 1.5835x over previous
#include <cuda_runtime.h>
#include <cuda_bf16.h>
#include <cstdint>

#define SEQ   512
#define BATCH 64
#define DIM   1024
#define HID   1024
#define NJ    4096            // 4 gates * HID
#define MROWS (SEQ*BATCH)     // 32768

// ---------------- scratch (static device allocs only) ----------------
__device__ float g_G[(size_t)SEQ * BATCH * NJ];          // [m][j] fp32 (x@Wx + biases)
__device__ __nv_bfloat16 g_Xs[(size_t)MROWS * 2048];     // [m][hi(1024)|lo(1024)]
__device__ __nv_bfloat16 g_Ws[(size_t)NJ * 2048];        // [j][hi|lo]  (Wx^T)
__device__ __nv_bfloat16 g_Whs[(size_t)NJ * 2048];       // [cb][hi|lo] (Wh^T, block-packed)
__device__ __nv_bfloat16 g_Hs[2][(size_t)BATCH * 2048];  // h staging [buf][b][hi|lo]
__device__ float g_bias[NJ];                             // bx+bh (gate-major j)
__device__ unsigned int g_bar_count;
__device__ unsigned int g_bar_gen;

struct GatePtrs {
    const float* Wx[4];
    const float* Wh[4];
    const float* bx[4];
    const float* bh[4];
};

// ---------------- small helpers ----------------
__device__ __forceinline__ uint32_t smem_to_u32(const void* p) {
    uint32_t a;
    asm("{ .reg .u64 t; cvta.to.shared.u64 t, %1; cvt.u32.u64 %0, t; }"
        : "=r"(a) : "l"(p));
    return a;
}
__device__ __forceinline__ void cp_async16(uint32_t saddr, const void* g) {
    asm volatile("cp.async.cg.shared.global [%0], [%1], 16;"
                 :: "r"(saddr), "l"(g) : "memory");
}
__device__ __forceinline__ void cp_commit() {
    asm volatile("cp.async.commit_group;" ::: "memory");
}
#define CP_WAIT2() asm volatile("cp.async.wait_group 2;" ::: "memory")
#define CP_WAIT1() asm volatile("cp.async.wait_group 1;" ::: "memory")
#define CP_WAIT0() asm volatile("cp.async.wait_group 0;" ::: "memory")

#define LDSM_X4(r0, r1, r2, r3, addr) \
    asm volatile("ldmatrix.sync.aligned.m8n8.x4.shared.b16 {%0,%1,%2,%3}, [%4];" \
        : "=r"(r0), "=r"(r1), "=r"(r2), "=r"(r3) : "r"(addr))

__device__ __forceinline__ void mma_bf16(float* c, const uint32_t* a, const uint32_t* b) {
    asm volatile(
        "mma.sync.aligned.m16n8k16.row.col.f32.bf16.bf16.f32 "
        "{%0,%1,%2,%3}, {%4,%5,%6,%7}, {%8,%9}, {%0,%1,%2,%3};"
        : "+f"(c[0]), "+f"(c[1]), "+f"(c[2]), "+f"(c[3])
        : "r"(a[0]), "r"(a[1]), "r"(a[2]), "r"(a[3]), "r"(b[0]), "r"(b[1]));
}

// smem addr with xor swizzle on 16B chunks (4 chunks per 64B row)
__device__ __forceinline__ uint32_t swz(uint32_t base, int row, int chunk) {
    return base + row * 64 + (((uint32_t)chunk ^ (((uint32_t)row >> 1) & 3)) << 4);
}

__device__ __forceinline__ float sigm(float v) {
    return 1.0f / (1.0f + expf(-v));
}

__device__ __forceinline__ void named_bar(int id, int nthreads) {
    asm volatile("bar.sync %0, %1;" :: "r"(id), "r"(nthreads) : "memory");
}

// ---------------- pack kernels ----------------
__global__ void pack_xs_kernel(const float* __restrict__ x) {
    int m = blockIdx.x;
    int k = threadIdx.x * 4;
    float4 v = *(const float4*)(x + (size_t)m * DIM + k);
    __nv_bfloat16 h0 = __float2bfloat16(v.x);
    __nv_bfloat16 h1 = __float2bfloat16(v.y);
    __nv_bfloat16 h2 = __float2bfloat16(v.z);
    __nv_bfloat16 h3 = __float2bfloat16(v.w);
    __nv_bfloat16 l0 = __float2bfloat16(v.x - __bfloat162float(h0));
    __nv_bfloat16 l1 = __float2bfloat16(v.y - __bfloat162float(h1));
    __nv_bfloat16 l2 = __float2bfloat16(v.z - __bfloat162float(h2));
    __nv_bfloat16 l3 = __float2bfloat16(v.w - __bfloat162float(h3));
    size_t base = (size_t)m * 2048 + k;
    *(__nv_bfloat162*)(g_Xs + base)            = __halves2bfloat162(h0, h1);
    *(__nv_bfloat162*)(g_Xs + base + 2)        = __halves2bfloat162(h2, h3);
    *(__nv_bfloat162*)(g_Xs + base + 1024)     = __halves2bfloat162(l0, l1);
    *(__nv_bfloat162*)(g_Xs + base + 1024 + 2) = __halves2bfloat162(l2, l3);
}

// Fused weight/bias pack: one kernel, grid-switched (keeps lstm_rec at launch #4)
//   blocks [0, 4096)     : Wx -> g_Ws   ([j][hi|lo], transposed)
//   blocks [4096, 8192)  : Wh -> g_Whs  (block-packed split)
//   blocks [8192, 8208)  : combined bias
__global__ void pack_w_kernel(GatePtrs p) {
    int bid = blockIdx.x;
    if (bid < 4096) {
        __shared__ float s[32][33];
        int kt = bid & 31, nt = (bid >> 5) & 31, g = bid >> 10;
        int tx = threadIdx.x & 31;
        int ty = threadIdx.x >> 5;
#pragma unroll
        for (int i = 0; i < 4; i++) {
            int r = ty + i * 8;
            s[r][tx] = p.Wx[g][(size_t)(kt * 32 + r) * 1024 + nt * 32 + tx];
        }
        __syncthreads();
#pragma unroll
        for (int i = 0; i < 4; i++) {
            int r2 = ty + i * 8;
            float v = s[tx][r2];
            __nv_bfloat16 hi = __float2bfloat16(v);
            __nv_bfloat16 lo = __float2bfloat16(v - __bfloat162float(hi));
            size_t j = (size_t)g * 1024 + nt * 32 + r2;
            size_t kcol = kt * 32 + tx;
            g_Ws[j * 2048 + kcol]        = hi;
            g_Ws[j * 2048 + 1024 + kcol] = lo;
        }
    } else if (bid < 8192) {
        int cb = bid - 4096;            // 0..4095
        int blk = cb >> 5;
        int c = cb & 31;
        int g = c >> 3;
        int col = blk * 8 + (c & 7);
        const float* W = p.Wh[g];
        int k0 = threadIdx.x * 4;
#pragma unroll
        for (int q = 0; q < 4; q++) {
            int k = k0 + q;
            float v = W[(size_t)k * 1024 + col];
            __nv_bfloat16 hi = __float2bfloat16(v);
            __nv_bfloat16 lo = __float2bfloat16(v - __bfloat162float(hi));
            g_Whs[(size_t)cb * 2048 + k]        = hi;
            g_Whs[(size_t)cb * 2048 + 1024 + k] = lo;
        }
    } else {
        int idx = (bid - 8192) * 256 + threadIdx.x;   // 0..4095
        int g = idx >> 10, n = idx & 1023;
        g_bias[idx] = p.bx[g][n] + p.bh[g][n];
    }
}

// ---------------- xproj: HMMA (mma.sync bf16) GEMM (proven R4 version) ----------------
#define BMT 256
#define BNT 128
#define BKT 32
#define STAGE_BYTES ((BMT + BNT) * BKT * 2)   // 24576
#define XP_SMEM (4 * STAGE_BYTES)             // 98304
#define NKI 96                                // 3072 / 32

__global__ __launch_bounds__(512, 1) void xproj_mma_kernel() {
    extern __shared__ char smem[];
    const uint32_t sbase = smem_to_u32(smem);
    const int tid = threadIdx.x;
    const int wid = tid >> 5;
    const int lid = tid & 31;

    const int mtile = blockIdx.x >> 5;
    const int ntile = blockIdx.x & 31;
    const int m0 = mtile * BMT;
    const int n0 = ntile * BNT;

    const int wm = wid >> 2;
    const int wn = wid & 3;

    int aRow[4], aSw[4];
#pragma unroll
    for (int mf = 0; mf < 4; mf++) {
        int r = wm * 64 + mf * 16 + (((lid >> 3) & 1) << 3) + (lid & 7);
        aRow[mf] = r * 64;
        aSw[mf] = (r >> 1) & 3;
    }
    const int aBit = lid >> 4;
    int bRow[2], bSw[2];
#pragma unroll
    for (int np = 0; np < 2; np++) {
        int r = wn * 32 + np * 16 + (((lid >> 4) & 1) << 3) + (lid & 7);
        bRow[np] = r * 64;
        bSw[np] = (r >> 1) & 3;
    }
    const int bBit = (lid >> 3) & 1;

    float acc[4][4][4];
#pragma unroll
    for (int mf = 0; mf < 4; mf++)
#pragma unroll
        for (int nf = 0; nf < 4; nf++)
#pragma unroll
            for (int q = 0; q < 4; q++) acc[mf][nf][q] = 0.0f;

    auto load_stage = [&](int kt, int st) {
        int seg = kt >> 5;
        int koff = (kt & 31) << 5;
        int a_col = koff + ((seg == 2) ? 1024 : 0);
        int b_col = koff + ((seg == 1) ? 1024 : 0);
        uint32_t sa = sbase + st * STAGE_BYTES;
        uint32_t sb = sa + BMT * BKT * 2;
#pragma unroll
        for (int i = 0; i < 3; i++) {
            int task = tid + i * 512;
            if (task < 1024) {
                int row = task >> 2, ch = task & 3;
                cp_async16(swz(sa, row, ch),
                           g_Xs + (size_t)(m0 + row) * 2048 + a_col + ch * 8);
            } else {
                int t2 = task - 1024;
                int row = t2 >> 2, ch = t2 & 3;
                cp_async16(swz(sb, row, ch),
                           g_Ws + (size_t)(n0 + row) * 2048 + b_col + ch * 8);
            }
        }
        cp_commit();
    };

    load_stage(0, 0);
    load_stage(1, 1);
    load_stage(2, 2);

    for (int kt = 0; kt < NKI; kt++) {
        CP_WAIT2();
        __syncthreads();
        if (kt + 3 < NKI) load_stage(kt + 3, (kt + 3) & 3);
        else cp_commit();

        uint32_t sa = sbase + (kt & 3) * STAGE_BYTES;
        uint32_t sb = sa + BMT * BKT * 2;

#pragma unroll
        for (int k16 = 0; k16 < 2; k16++) {
            uint32_t bf[4][2];
#pragma unroll
            for (int np = 0; np < 2; np++) {
                uint32_t addr = sb + bRow[np]
                              + (((uint32_t)(k16 * 2 + bBit) ^ bSw[np]) << 4);
                uint32_t r0, r1, r2, r3;
                LDSM_X4(r0, r1, r2, r3, addr);
                bf[np * 2][0] = r0; bf[np * 2][1] = r1;
                bf[np * 2 + 1][0] = r2; bf[np * 2 + 1][1] = r3;
            }
#pragma unroll
            for (int mf = 0; mf < 4; mf++) {
                uint32_t af[4];
                uint32_t addr = sa + aRow[mf]
                              + (((uint32_t)(k16 * 2 + aBit) ^ aSw[mf]) << 4);
                LDSM_X4(af[0], af[1], af[2], af[3], addr);
#pragma unroll
                for (int nf = 0; nf < 4; nf++)
                    mma_bf16(acc[mf][nf], af, bf[nf]);
            }
        }
    }

    const int row_base = m0 + wm * 64 + (lid >> 2);
    const int col_base = n0 + wn * 32 + (lid & 3) * 2;
#pragma unroll
    for (int nf = 0; nf < 4; nf++) {
        int col = col_base + nf * 8;
        float2 bb = *(const float2*)&g_bias[col];
#pragma unroll
        for (int mf = 0; mf < 4; mf++) {
            int r = row_base + mf * 16;
            float2 v0 = make_float2(acc[mf][nf][0] + bb.x, acc[mf][nf][1] + bb.y);
            float2 v1 = make_float2(acc[mf][nf][2] + bb.x, acc[mf][nf][3] + bb.y);
            *(float2*)&g_G[(size_t)r * NJ + col]       = v0;
            *(float2*)&g_G[(size_t)(r + 8) * NJ + col] = v1;
        }
    }
}

// ---------------- persistent recurrence (R6 config: best known) ----------------
// 128 blocks x 512 threads. Block owns 8 hidden cols (32 gate-cols).
// warp = (wm 0..3 [m16], wn 0..1 [n16], ks 0..1 [K half]).
// Wh split resident in SMEM. A(h) chunks staged per (wm,ks) pair via cp.async
// ring (depth-2, CP_WAIT1), one 64-thread named barrier per chunk.
// Atomic-counter grid barrier. G[t+1] prefetched before the barrier.
#define RB 128
#define RSM_B     0            // 64 chunks * 2048B = 131072
#define RSM_A     131072       // 8 pairs * 4 stages * 2048B = 65536
#define RSM_PRE   196608       // 64*33 floats = 8448
#define RSM_PRE2  205056       // 64*33 floats = 8448
#define RSM_TOTAL 213504

__global__ __launch_bounds__(512, 1) void lstm_rec_kernel(float* __restrict__ out) {
    extern __shared__ char smem[];
    const uint32_t sbase = smem_to_u32(smem);
    const uint32_t Bbase = sbase + RSM_B;
    float* pre_s  = (float*)(smem + RSM_PRE);    // ks=0 partials [64][33]
    float* pre2_s = (float*)(smem + RSM_PRE2);   // ks=1 partials [64][33]

    const int tid = threadIdx.x;
    const int wid = tid >> 5;
    const int lid = tid & 31;
    const int blk = blockIdx.x;

    // warp coords: wid = ks*8 + wn*4 + wm
    const int wm = wid & 3;
    const int wn = (wid >> 2) & 1;
    const int ks = wid >> 3;
    const int pairid = ks * 4 + wm;                  // 0..7
    const uint32_t Apair = sbase + RSM_A + pairid * 8192;

    // ldmatrix lane addresses (A region: 16 rows x 64B; B chunks: 32 rows x 64B)
    const int arow = (((lid >> 3) & 1) << 3) + (lid & 7);
    const int aR = arow * 64, aS = (arow >> 1) & 3;
    const int aBit = lid >> 4;
    const int brow = wn * 16 + (((lid >> 4) & 1) << 3) + (lid & 7);
    const int bR = brow * 64, bS = (brow >> 1) & 3;
    const int bBit = (lid >> 3) & 1;

    // gate-thread mapping: 512 threads -> (b 0..63, oc 0..7)
    const int oc = tid & 7;
    const int b = tid >> 3;
    const int ncol = blk * 8 + oc;

    float* out_hseq = out;
    float* out_h = out + (size_t)SEQ * BATCH * HID;
    float* out_c = out_h + BATCH * HID;

    // ---- preload Wh split into smem: 64 chunks of 32 rows x 32 k ----
#pragma unroll 4
    for (int i = 0; i < 16; i++) {
        int task = tid + i * 512;           // 0..8191
        int chunk = task >> 7;
        int rem = task & 127;
        int r = rem >> 2;
        int ci = rem & 3;
        int col = (chunk < 32) ? chunk * 32 : 1024 + (chunk - 32) * 32;
        cp_async16(swz(Bbase + chunk * 2048, r, ci),
                   g_Whs + (size_t)(blk * 32 + r) * 2048 + col + ci * 8);
    }
    cp_commit();
    CP_WAIT0();
    __syncthreads();

    float cst = 0.0f;    // per-thread cell state (one (b, ncol) pair)

    // G[0] prefetch
    float gpre[4];
    {
        const float* Gt = g_G + (size_t)b * NJ + ncol;
#pragma unroll
        for (int g = 0; g < 4; g++)
            gpre[g] = __ldg(Gt + g * 1024);
    }

    for (int t = 0; t < SEQ; t++) {
        const __nv_bfloat16* hprev = g_Hs[(t - 1) & 1];

        float acc[2][4];
#pragma unroll
        for (int nf = 0; nf < 2; nf++)
#pragma unroll
            for (int q = 0; q < 4; q++) acc[nf][q] = 0.0f;

        if (t > 0) {
            // per-warp chunk loader (pair-shared region; each warp loads half)
            auto load_chunk = [&](int c) {
                if (c < 16) {
                    uint32_t st = Apair + (c & 3) * 2048;
                    int k0 = ks * 512 + c * 32;
#pragma unroll
                    for (int i = 0; i < 2; i++) {
                        int idx = wn * 64 + lid + i * 32;    // 0..127 across pair
                        int half = idx >> 6;                 // 0 hi, 1 lo
                        int rr = idx & 63;
                        int r = rr >> 2, ch = rr & 3;
                        cp_async16(swz(st + half * 1024, r, ch),
                                   hprev + (size_t)(wm * 16 + r) * 2048
                                         + half * 1024 + k0 + ch * 8);
                    }
                }
                cp_commit();
            };

            load_chunk(0);
            load_chunk(1);

            for (int c = 0; c < 16; c++) {
                CP_WAIT1();
                named_bar(1 + pairid, 64);
                load_chunk(c + 2);

                uint32_t AH = Apair + (c & 3) * 2048;
                uint32_t AL = AH + 1024;
                uint32_t BH = Bbase + (ks * 16 + c) * 2048;
                uint32_t BL = Bbase + (32 + ks * 16 + c) * 2048;

#pragma unroll
                for (int k16 = 0; k16 < 2; k16++) {
                    uint32_t aOff = (((uint32_t)(k16 * 2 + aBit) ^ aS) << 4);
                    uint32_t bOff = (((uint32_t)(k16 * 2 + bBit) ^ bS) << 4);
                    uint32_t af[4], al[4];
                    LDSM_X4(af[0], af[1], af[2], af[3], AH + aR + aOff);
                    LDSM_X4(al[0], al[1], al[2], al[3], AL + aR + aOff);
                    uint32_t r0, r1, r2, r3;
                    LDSM_X4(r0, r1, r2, r3, BH + bR + bOff);
                    uint32_t bh0[2] = {r0, r1}, bh1[2] = {r2, r3};
                    mma_bf16(acc[0], af, bh0);
                    mma_bf16(acc[1], af, bh1);
                    mma_bf16(acc[0], al, bh0);
                    mma_bf16(acc[1], al, bh1);
                    LDSM_X4(r0, r1, r2, r3, BL + bR + bOff);
                    uint32_t bl0[2] = {r0, r1}, bl1[2] = {r2, r3};
                    mma_bf16(acc[0], af, bl0);
                    mma_bf16(acc[1], af, bl1);
                }
            }
        }

        // write partial fragments
        {
            float* dst = ks ? pre2_s : pre_s;
            int r = wm * 16 + (lid >> 2);
            int cb2 = wn * 16 + (lid & 3) * 2;
#pragma unroll
            for (int nf = 0; nf < 2; nf++) {
                int c = cb2 + nf * 8;
                dst[r * 33 + c]           = acc[nf][0];
                dst[r * 33 + c + 1]       = acc[nf][1];
                dst[(r + 8) * 33 + c]     = acc[nf][2];
                dst[(r + 8) * 33 + c + 1] = acc[nf][3];
            }
        }
        __syncthreads();

        // gate math: pre cols [f0..7 | i0..7 | o0..7 | g0..7]
        {
            float pf = pre_s[b * 33 + oc]      + pre2_s[b * 33 + oc]      + gpre[0];
            float pi = pre_s[b * 33 + 8 + oc]  + pre2_s[b * 33 + 8 + oc]  + gpre[1];
            float po = pre_s[b * 33 + 16 + oc] + pre2_s[b * 33 + 16 + oc] + gpre[2];
            float pg = pre_s[b * 33 + 24 + oc] + pre2_s[b * 33 + 24 + oc] + gpre[3];

            float f = sigm(pf);
            float i = sigm(pi);
            float o = sigm(po);
            float g = tanhf(pg);
            cst = f * cst + i * g;
            float h = o * tanhf(cst);

            // h staging first (critical path for next step), then output
            __nv_bfloat16* Hc = g_Hs[t & 1];
            __nv_bfloat16 hhi = __float2bfloat16(h);
            Hc[(size_t)b * 2048 + ncol]        = hhi;
            Hc[(size_t)b * 2048 + 1024 + ncol] =
                __float2bfloat16(h - __bfloat162float(hhi));

            out_hseq[(size_t)t * BATCH * HID + (size_t)b * HID + ncol] = h;

            if (t == SEQ - 1) {
                out_h[(size_t)b * HID + ncol] = h;
                out_c[(size_t)b * HID + ncol] = cst;
            }
        }

        // prefetch G[t+1] (independent of h(t)) so it overlaps the barrier
        if (t < SEQ - 1) {
            const float* Gt = g_G + (size_t)(t + 1) * BATCH * NJ + (size_t)b * NJ + ncol;
#pragma unroll
            for (int g = 0; g < 4; g++)
                gpre[g] = __ldg(Gt + g * 1024);

            // grid barrier (atomic counter + gen poll — best measured)
            __threadfence();
            __syncthreads();
            if (tid == 0) {
                unsigned gen = *(volatile unsigned int*)&g_bar_gen;
                unsigned arrived = atomicAdd(&g_bar_count, 1u);
                if (arrived == RB - 1) {
                    g_bar_count = 0u;
                    __threadfence();
                    atomicAdd(&g_bar_gen, 1u);
                } else {
                    while (*(volatile unsigned int*)&g_bar_gen == gen) {
                        __nanosleep(32);
                    }
                }
            }
            __syncthreads();
        }
    }
}

// ---------------- launch ----------------
extern "C" void kernel_launch(void* const* d_in, const int* in_sizes, int n_in,
                              void* d_out, int out_size) {
    const float* x = nullptr;
    const float* W[8] = {};
    const float* Bv[8] = {};
    int wi = 0, bi = 0;
    for (int i = 0; i < n_in; i++) {
        long long sz = in_sizes[i];
        if (sz == (long long)SEQ * BATCH * DIM) {
            x = (const float*)d_in[i];
        } else if (sz == (long long)DIM * HID) {
            if (wi < 8) W[wi++] = (const float*)d_in[i];
        } else if (sz == HID) {
            if (bi < 8) Bv[bi++] = (const float*)d_in[i];
        }
    }
    if (!x || wi != 8 || bi != 8) return;

    GatePtrs p;
    for (int g = 0; g < 4; g++) {
        p.Wx[g] = W[g];
        p.Wh[g] = W[4 + g];
        p.bx[g] = Bv[g];
        p.bh[g] = Bv[4 + g];
    }

    float* outf = (float*)d_out;

    cudaFuncSetAttribute(xproj_mma_kernel,
                         cudaFuncAttributeMaxDynamicSharedMemorySize, XP_SMEM);
    cudaFuncSetAttribute(lstm_rec_kernel,
                         cudaFuncAttributeMaxDynamicSharedMemorySize, RSM_TOTAL);

    // 4 launches total — profiler's capture slot (#4) lands on lstm_rec_kernel
    pack_xs_kernel<<<MROWS, 256>>>(x);          // 1
    pack_w_kernel<<<8208, 256>>>(p);            // 2 (fused Ws/Whs/bias)
    xproj_mma_kernel<<<128 * 32, 512, XP_SMEM>>>();   // 3
    lstm_rec_kernel<<<RB, 512, RSM_TOTAL>>>(outf);    // 4
}

// round 11
// speedup vs baseline: 1.6868x; 1.0652x over previous
#include <cuda_runtime.h>
#include <cuda_bf16.h>
#include <cstdint>

#define SEQ   512
#define BATCH 64
#define DIM   1024
#define HID   1024
#define NJ    4096            // 4 gates * HID
#define MROWS (SEQ*BATCH)     // 32768

// ---------------- scratch (static device allocs only) ----------------
__device__ float g_G[(size_t)SEQ * BATCH * NJ];          // [m][j] fp32 (x@Wx + biases)
__device__ __nv_bfloat16 g_Xs[(size_t)MROWS * 2048];     // [m][hi(1024)|lo(1024)]
__device__ __nv_bfloat16 g_Ws[(size_t)NJ * 2048];        // [j][hi|lo]  (Wx^T)
__device__ __nv_bfloat16 g_Whs[(size_t)NJ * 2048];       // [cb][hi|lo] (Wh^T, block-packed)
__device__ __nv_bfloat16 g_Hs[2][(size_t)BATCH * 2048];  // h staging [buf][b][hi|lo]
__device__ float g_bias[NJ];                             // bx+bh (gate-major j)
__device__ unsigned int g_bar_count;
__device__ unsigned int g_bar_gen;

struct GatePtrs {
    const float* Wx[4];
    const float* Wh[4];
    const float* bx[4];
    const float* bh[4];
};

// ---------------- small helpers ----------------
__device__ __forceinline__ uint32_t smem_to_u32(const void* p) {
    uint32_t a;
    asm("{ .reg .u64 t; cvta.to.shared.u64 t, %1; cvt.u32.u64 %0, t; }"
        : "=r"(a) : "l"(p));
    return a;
}
__device__ __forceinline__ void cp_async16(uint32_t saddr, const void* g) {
    asm volatile("cp.async.cg.shared.global [%0], [%1], 16;"
                 :: "r"(saddr), "l"(g) : "memory");
}
__device__ __forceinline__ void cp_commit() {
    asm volatile("cp.async.commit_group;" ::: "memory");
}
#define CP_WAIT2() asm volatile("cp.async.wait_group 2;" ::: "memory")
#define CP_WAIT1() asm volatile("cp.async.wait_group 1;" ::: "memory")
#define CP_WAIT0() asm volatile("cp.async.wait_group 0;" ::: "memory")

#define LDSM_X4(r0, r1, r2, r3, addr) \
    asm volatile("ldmatrix.sync.aligned.m8n8.x4.shared.b16 {%0,%1,%2,%3}, [%4];" \
        : "=r"(r0), "=r"(r1), "=r"(r2), "=r"(r3) : "r"(addr))

__device__ __forceinline__ void mma_bf16(float* c, const uint32_t* a, const uint32_t* b) {
    asm volatile(
        "mma.sync.aligned.m16n8k16.row.col.f32.bf16.bf16.f32 "
        "{%0,%1,%2,%3}, {%4,%5,%6,%7}, {%8,%9}, {%0,%1,%2,%3};"
        : "+f"(c[0]), "+f"(c[1]), "+f"(c[2]), "+f"(c[3])
        : "r"(a[0]), "r"(a[1]), "r"(a[2]), "r"(a[3]), "r"(b[0]), "r"(b[1]));
}

// smem addr with xor swizzle on 16B chunks (4 chunks per 64B row)
__device__ __forceinline__ uint32_t swz(uint32_t base, int row, int chunk) {
    return base + row * 64 + (((uint32_t)chunk ^ (((uint32_t)row >> 1) & 3)) << 4);
}

__device__ __forceinline__ float sigm(float v) {
    return 1.0f / (1.0f + expf(-v));
}

__device__ __forceinline__ void named_bar(int id, int nthreads) {
    asm volatile("bar.sync %0, %1;" :: "r"(id), "r"(nthreads) : "memory");
}

// ---------------- pack kernels ----------------
__global__ void pack_xs_kernel(const float* __restrict__ x) {
    int m = blockIdx.x;
    int k = threadIdx.x * 4;
    float4 v = *(const float4*)(x + (size_t)m * DIM + k);
    __nv_bfloat16 h0 = __float2bfloat16(v.x);
    __nv_bfloat16 h1 = __float2bfloat16(v.y);
    __nv_bfloat16 h2 = __float2bfloat16(v.z);
    __nv_bfloat16 h3 = __float2bfloat16(v.w);
    __nv_bfloat16 l0 = __float2bfloat16(v.x - __bfloat162float(h0));
    __nv_bfloat16 l1 = __float2bfloat16(v.y - __bfloat162float(h1));
    __nv_bfloat16 l2 = __float2bfloat16(v.z - __bfloat162float(h2));
    __nv_bfloat16 l3 = __float2bfloat16(v.w - __bfloat162float(h3));
    size_t base = (size_t)m * 2048 + k;
    *(__nv_bfloat162*)(g_Xs + base)            = __halves2bfloat162(h0, h1);
    *(__nv_bfloat162*)(g_Xs + base + 2)        = __halves2bfloat162(h2, h3);
    *(__nv_bfloat162*)(g_Xs + base + 1024)     = __halves2bfloat162(l0, l1);
    *(__nv_bfloat162*)(g_Xs + base + 1024 + 2) = __halves2bfloat162(l2, l3);
}

// Fused weight/bias pack: one kernel, grid-switched (keeps lstm_rec at launch #4)
//   blocks [0, 4096)     : Wx -> g_Ws   ([j][hi|lo], transposed)
//   blocks [4096, 8192)  : Wh -> g_Whs  (block-packed split)
//   blocks [8192, 8208)  : combined bias
__global__ void pack_w_kernel(GatePtrs p) {
    int bid = blockIdx.x;
    if (bid < 4096) {
        __shared__ float s[32][33];
        int kt = bid & 31, nt = (bid >> 5) & 31, g = bid >> 10;
        int tx = threadIdx.x & 31;
        int ty = threadIdx.x >> 5;
#pragma unroll
        for (int i = 0; i < 4; i++) {
            int r = ty + i * 8;
            s[r][tx] = p.Wx[g][(size_t)(kt * 32 + r) * 1024 + nt * 32 + tx];
        }
        __syncthreads();
#pragma unroll
        for (int i = 0; i < 4; i++) {
            int r2 = ty + i * 8;
            float v = s[tx][r2];
            __nv_bfloat16 hi = __float2bfloat16(v);
            __nv_bfloat16 lo = __float2bfloat16(v - __bfloat162float(hi));
            size_t j = (size_t)g * 1024 + nt * 32 + r2;
            size_t kcol = kt * 32 + tx;
            g_Ws[j * 2048 + kcol]        = hi;
            g_Ws[j * 2048 + 1024 + kcol] = lo;
        }
    } else if (bid < 8192) {
        int cb = bid - 4096;            // 0..4095
        int blk = cb >> 5;
        int c = cb & 31;
        int g = c >> 3;
        int col = blk * 8 + (c & 7);
        const float* W = p.Wh[g];
        int k0 = threadIdx.x * 4;
#pragma unroll
        for (int q = 0; q < 4; q++) {
            int k = k0 + q;
            float v = W[(size_t)k * 1024 + col];
            __nv_bfloat16 hi = __float2bfloat16(v);
            __nv_bfloat16 lo = __float2bfloat16(v - __bfloat162float(hi));
            g_Whs[(size_t)cb * 2048 + k]        = hi;
            g_Whs[(size_t)cb * 2048 + 1024 + k] = lo;
        }
    } else {
        int idx = (bid - 8192) * 256 + threadIdx.x;   // 0..4095
        int g = idx >> 10, n = idx & 1023;
        g_bias[idx] = p.bx[g][n] + p.bh[g][n];
    }
}

// ---------------- xproj: HMMA (mma.sync bf16) GEMM, 2 blocks/SM ----------------
// BMT=128, BNT=128, 256 threads, launch_bounds (256,2) -> co-resident blocks
// Per-warp fragment code identical to the proven R4 version (64m x 32n per warp).
#define BMT 128
#define BNT 128
#define BKT 32
#define STAGE_BYTES ((BMT + BNT) * BKT * 2)   // 16384
#define XP_SMEM (4 * STAGE_BYTES)             // 65536
#define NKI 96                                // 3072 / 32

__global__ __launch_bounds__(256, 2) void xproj_mma_kernel() {
    extern __shared__ char smem[];
    const uint32_t sbase = smem_to_u32(smem);
    const int tid = threadIdx.x;
    const int wid = tid >> 5;        // 0..7
    const int lid = tid & 31;

    const int mtile = blockIdx.x >> 5;   // 0..255
    const int ntile = blockIdx.x & 31;   // 0..31
    const int m0 = mtile * BMT;
    const int n0 = ntile * BNT;

    const int wm = wid >> 2;   // 0..1  (64 rows each)
    const int wn = wid & 3;    // 0..3  (32 cols each)

    int aRow[4], aSw[4];
#pragma unroll
    for (int mf = 0; mf < 4; mf++) {
        int r = wm * 64 + mf * 16 + (((lid >> 3) & 1) << 3) + (lid & 7);
        aRow[mf] = r * 64;
        aSw[mf] = (r >> 1) & 3;
    }
    const int aBit = lid >> 4;
    int bRow[2], bSw[2];
#pragma unroll
    for (int np = 0; np < 2; np++) {
        int r = wn * 32 + np * 16 + (((lid >> 4) & 1) << 3) + (lid & 7);
        bRow[np] = r * 64;
        bSw[np] = (r >> 1) & 3;
    }
    const int bBit = (lid >> 3) & 1;

    float acc[4][4][4];
#pragma unroll
    for (int mf = 0; mf < 4; mf++)
#pragma unroll
        for (int nf = 0; nf < 4; nf++)
#pragma unroll
            for (int q = 0; q < 4; q++) acc[mf][nf][q] = 0.0f;

    // stage loader: A 512 tasks + B 512 tasks, 4 x 16B per thread
    auto load_stage = [&](int kt, int st) {
        int seg = kt >> 5;
        int koff = (kt & 31) << 5;
        int a_col = koff + ((seg == 2) ? 1024 : 0);
        int b_col = koff + ((seg == 1) ? 1024 : 0);
        uint32_t sa = sbase + st * STAGE_BYTES;
        uint32_t sb = sa + BMT * BKT * 2;
#pragma unroll
        for (int i = 0; i < 4; i++) {
            int task = tid + i * 256;
            if (task < 512) {
                int row = task >> 2, ch = task & 3;
                cp_async16(swz(sa, row, ch),
                           g_Xs + (size_t)(m0 + row) * 2048 + a_col + ch * 8);
            } else {
                int t2 = task - 512;
                int row = t2 >> 2, ch = t2 & 3;
                cp_async16(swz(sb, row, ch),
                           g_Ws + (size_t)(n0 + row) * 2048 + b_col + ch * 8);
            }
        }
        cp_commit();
    };

    load_stage(0, 0);
    load_stage(1, 1);
    load_stage(2, 2);

    for (int kt = 0; kt < NKI; kt++) {
        CP_WAIT2();
        __syncthreads();
        if (kt + 3 < NKI) load_stage(kt + 3, (kt + 3) & 3);
        else cp_commit();

        uint32_t sa = sbase + (kt & 3) * STAGE_BYTES;
        uint32_t sb = sa + BMT * BKT * 2;

#pragma unroll
        for (int k16 = 0; k16 < 2; k16++) {
            uint32_t bf[4][2];
#pragma unroll
            for (int np = 0; np < 2; np++) {
                uint32_t addr = sb + bRow[np]
                              + (((uint32_t)(k16 * 2 + bBit) ^ bSw[np]) << 4);
                uint32_t r0, r1, r2, r3;
                LDSM_X4(r0, r1, r2, r3, addr);
                bf[np * 2][0] = r0; bf[np * 2][1] = r1;
                bf[np * 2 + 1][0] = r2; bf[np * 2 + 1][1] = r3;
            }
#pragma unroll
            for (int mf = 0; mf < 4; mf++) {
                uint32_t af[4];
                uint32_t addr = sa + aRow[mf]
                              + (((uint32_t)(k16 * 2 + aBit) ^ aSw[mf]) << 4);
                LDSM_X4(af[0], af[1], af[2], af[3], addr);
#pragma unroll
                for (int nf = 0; nf < 4; nf++)
                    mma_bf16(acc[mf][nf], af, bf[nf]);
            }
        }
    }

    const int row_base = m0 + wm * 64 + (lid >> 2);
    const int col_base = n0 + wn * 32 + (lid & 3) * 2;
#pragma unroll
    for (int nf = 0; nf < 4; nf++) {
        int col = col_base + nf * 8;
        float2 bb = *(const float2*)&g_bias[col];
#pragma unroll
        for (int mf = 0; mf < 4; mf++) {
            int r = row_base + mf * 16;
            float2 v0 = make_float2(acc[mf][nf][0] + bb.x, acc[mf][nf][1] + bb.y);
            float2 v1 = make_float2(acc[mf][nf][2] + bb.x, acc[mf][nf][3] + bb.y);
            *(float2*)&g_G[(size_t)r * NJ + col]       = v0;
            *(float2*)&g_G[(size_t)(r + 8) * NJ + col] = v1;
        }
    }
}

// ---------------- persistent recurrence (R10 config: best measured) ----------------
#define RB 128
#define RSM_B     0            // 64 chunks * 2048B = 131072
#define RSM_A     131072       // 8 pairs * 4 stages * 2048B = 65536
#define RSM_PRE   196608       // 64*33 floats = 8448
#define RSM_PRE2  205056       // 64*33 floats = 8448
#define RSM_TOTAL 213504

__global__ __launch_bounds__(512, 1) void lstm_rec_kernel(float* __restrict__ out) {
    extern __shared__ char smem[];
    const uint32_t sbase = smem_to_u32(smem);
    const uint32_t Bbase = sbase + RSM_B;
    float* pre_s  = (float*)(smem + RSM_PRE);    // ks=0 partials [64][33]
    float* pre2_s = (float*)(smem + RSM_PRE2);   // ks=1 partials [64][33]

    const int tid = threadIdx.x;
    const int wid = tid >> 5;
    const int lid = tid & 31;
    const int blk = blockIdx.x;

    // warp coords: wid = ks*8 + wn*4 + wm
    const int wm = wid & 3;
    const int wn = (wid >> 2) & 1;
    const int ks = wid >> 3;
    const int pairid = ks * 4 + wm;                  // 0..7
    const uint32_t Apair = sbase + RSM_A + pairid * 8192;

    // ldmatrix lane addresses (A region: 16 rows x 64B; B chunks: 32 rows x 64B)
    const int arow = (((lid >> 3) & 1) << 3) + (lid & 7);
    const int aR = arow * 64, aS = (arow >> 1) & 3;
    const int aBit = lid >> 4;
    const int brow = wn * 16 + (((lid >> 4) & 1) << 3) + (lid & 7);
    const int bR = brow * 64, bS = (brow >> 1) & 3;
    const int bBit = (lid >> 3) & 1;

    // gate-thread mapping: 512 threads -> (b 0..63, oc 0..7)
    const int oc = tid & 7;
    const int b = tid >> 3;
    const int ncol = blk * 8 + oc;

    float* out_hseq = out;
    float* out_h = out + (size_t)SEQ * BATCH * HID;
    float* out_c = out_h + BATCH * HID;

    // ---- preload Wh split into smem: 64 chunks of 32 rows x 32 k ----
#pragma unroll 4
    for (int i = 0; i < 16; i++) {
        int task = tid + i * 512;           // 0..8191
        int chunk = task >> 7;
        int rem = task & 127;
        int r = rem >> 2;
        int ci = rem & 3;
        int col = (chunk < 32) ? chunk * 32 : 1024 + (chunk - 32) * 32;
        cp_async16(swz(Bbase + chunk * 2048, r, ci),
                   g_Whs + (size_t)(blk * 32 + r) * 2048 + col + ci * 8);
    }
    cp_commit();
    CP_WAIT0();
    __syncthreads();

    float cst = 0.0f;    // per-thread cell state (one (b, ncol) pair)

    // G[0] prefetch
    float gpre[4];
    {
        const float* Gt = g_G + (size_t)b * NJ + ncol;
#pragma unroll
        for (int g = 0; g < 4; g++)
            gpre[g] = __ldg(Gt + g * 1024);
    }

    for (int t = 0; t < SEQ; t++) {
        const __nv_bfloat16* hprev = g_Hs[(t - 1) & 1];

        float acc[2][4];
#pragma unroll
        for (int nf = 0; nf < 2; nf++)
#pragma unroll
            for (int q = 0; q < 4; q++) acc[nf][q] = 0.0f;

        if (t > 0) {
            // per-warp chunk loader (pair-shared region; each warp loads half)
            auto load_chunk = [&](int c) {
                if (c < 16) {
                    uint32_t st = Apair + (c & 3) * 2048;
                    int k0 = ks * 512 + c * 32;
#pragma unroll
                    for (int i = 0; i < 2; i++) {
                        int idx = wn * 64 + lid + i * 32;    // 0..127 across pair
                        int half = idx >> 6;                 // 0 hi, 1 lo
                        int rr = idx & 63;
                        int r = rr >> 2, ch = rr & 3;
                        cp_async16(swz(st + half * 1024, r, ch),
                                   hprev + (size_t)(wm * 16 + r) * 2048
                                         + half * 1024 + k0 + ch * 8);
                    }
                }
                cp_commit();
            };

            load_chunk(0);
            load_chunk(1);

            for (int c = 0; c < 16; c++) {
                CP_WAIT1();
                named_bar(1 + pairid, 64);
                load_chunk(c + 2);

                uint32_t AH = Apair + (c & 3) * 2048;
                uint32_t AL = AH + 1024;
                uint32_t BH = Bbase + (ks * 16 + c) * 2048;
                uint32_t BL = Bbase + (32 + ks * 16 + c) * 2048;

#pragma unroll
                for (int k16 = 0; k16 < 2; k16++) {
                    uint32_t aOff = (((uint32_t)(k16 * 2 + aBit) ^ aS) << 4);
                    uint32_t bOff = (((uint32_t)(k16 * 2 + bBit) ^ bS) << 4);
                    uint32_t af[4], al[4];
                    LDSM_X4(af[0], af[1], af[2], af[3], AH + aR + aOff);
                    LDSM_X4(al[0], al[1], al[2], al[3], AL + aR + aOff);
                    uint32_t r0, r1, r2, r3;
                    LDSM_X4(r0, r1, r2, r3, BH + bR + bOff);
                    uint32_t bh0[2] = {r0, r1}, bh1[2] = {r2, r3};
                    mma_bf16(acc[0], af, bh0);
                    mma_bf16(acc[1], af, bh1);
                    mma_bf16(acc[0], al, bh0);
                    mma_bf16(acc[1], al, bh1);
                    LDSM_X4(r0, r1, r2, r3, BL + bR + bOff);
                    uint32_t bl0[2] = {r0, r1}, bl1[2] = {r2, r3};
                    mma_bf16(acc[0], af, bl0);
                    mma_bf16(acc[1], af, bl1);
                }
            }
        }

        // write partial fragments
        {
            float* dst = ks ? pre2_s : pre_s;
            int r = wm * 16 + (lid >> 2);
            int cb2 = wn * 16 + (lid & 3) * 2;
#pragma unroll
            for (int nf = 0; nf < 2; nf++) {
                int c = cb2 + nf * 8;
                dst[r * 33 + c]           = acc[nf][0];
                dst[r * 33 + c + 1]       = acc[nf][1];
                dst[(r + 8) * 33 + c]     = acc[nf][2];
                dst[(r + 8) * 33 + c + 1] = acc[nf][3];
            }
        }
        __syncthreads();

        // gate math: pre cols [f0..7 | i0..7 | o0..7 | g0..7]
        {
            float pf = pre_s[b * 33 + oc]      + pre2_s[b * 33 + oc]      + gpre[0];
            float pi = pre_s[b * 33 + 8 + oc]  + pre2_s[b * 33 + 8 + oc]  + gpre[1];
            float po = pre_s[b * 33 + 16 + oc] + pre2_s[b * 33 + 16 + oc] + gpre[2];
            float pg = pre_s[b * 33 + 24 + oc] + pre2_s[b * 33 + 24 + oc] + gpre[3];

            float f = sigm(pf);
            float i = sigm(pi);
            float o = sigm(po);
            float g = tanhf(pg);
            cst = f * cst + i * g;
            float h = o * tanhf(cst);

            // h staging first (critical path for next step), then output
            __nv_bfloat16* Hc = g_Hs[t & 1];
            __nv_bfloat16 hhi = __float2bfloat16(h);
            Hc[(size_t)b * 2048 + ncol]        = hhi;
            Hc[(size_t)b * 2048 + 1024 + ncol] =
                __float2bfloat16(h - __bfloat162float(hhi));

            out_hseq[(size_t)t * BATCH * HID + (size_t)b * HID + ncol] = h;

            if (t == SEQ - 1) {
                out_h[(size_t)b * HID + ncol] = h;
                out_c[(size_t)b * HID + ncol] = cst;
            }
        }

        // prefetch G[t+1] (independent of h(t)) so it overlaps the barrier
        if (t < SEQ - 1) {
            const float* Gt = g_G + (size_t)(t + 1) * BATCH * NJ + (size_t)b * NJ + ncol;
#pragma unroll
            for (int g = 0; g < 4; g++)
                gpre[g] = __ldg(Gt + g * 1024);

            // grid barrier (atomic counter + gen poll — best measured)
            __threadfence();
            __syncthreads();
            if (tid == 0) {
                unsigned gen = *(volatile unsigned int*)&g_bar_gen;
                unsigned arrived = atomicAdd(&g_bar_count, 1u);
                if (arrived == RB - 1) {
                    g_bar_count = 0u;
                    __threadfence();
                    atomicAdd(&g_bar_gen, 1u);
                } else {
                    while (*(volatile unsigned int*)&g_bar_gen == gen) {
                        __nanosleep(32);
                    }
                }
            }
            __syncthreads();
        }
    }
}

// ---------------- launch ----------------
extern "C" void kernel_launch(void* const* d_in, const int* in_sizes, int n_in,
                              void* d_out, int out_size) {
    const float* x = nullptr;
    const float* W[8] = {};
    const float* Bv[8] = {};
    int wi = 0, bi = 0;
    for (int i = 0; i < n_in; i++) {
        long long sz = in_sizes[i];
        if (sz == (long long)SEQ * BATCH * DIM) {
            x = (const float*)d_in[i];
        } else if (sz == (long long)DIM * HID) {
            if (wi < 8) W[wi++] = (const float*)d_in[i];
        } else if (sz == HID) {
            if (bi < 8) Bv[bi++] = (const float*)d_in[i];
        }
    }
    if (!x || wi != 8 || bi != 8) return;

    GatePtrs p;
    for (int g = 0; g < 4; g++) {
        p.Wx[g] = W[g];
        p.Wh[g] = W[4 + g];
        p.bx[g] = Bv[g];
        p.bh[g] = Bv[4 + g];
    }

    float* outf = (float*)d_out;

    cudaFuncSetAttribute(xproj_mma_kernel,
                         cudaFuncAttributeMaxDynamicSharedMemorySize, XP_SMEM);
    cudaFuncSetAttribute(lstm_rec_kernel,
                         cudaFuncAttributeMaxDynamicSharedMemorySize, RSM_TOTAL);

    // 4 launches total — profiler's capture slot (#4) lands on lstm_rec_kernel
    pack_xs_kernel<<<MROWS, 256>>>(x);             // 1
    pack_w_kernel<<<8208, 256>>>(p);               // 2 (fused Ws/Whs/bias)
    xproj_mma_kernel<<<256 * 32, 256, XP_SMEM>>>();// 3 (2 blocks/SM)
    lstm_rec_kernel<<<RB, 512, RSM_TOTAL>>>(outf); // 4
}